// round 6
// baseline (speedup 1.0000x reference)
#include <cuda_runtime.h>
#include <cstdint>

// Problem constants
#define Bz   8192
#define Tz   512
#define Dz   8
#define Hz   64
#define Gz   256      // 4*H
#define BT   64       // batch tile per CTA
#define NCTA 128      // Bz / BT
#define NTHR 256

// SMEM layout (floats), transposed state with row stride 68 (pad keeps 16B align,
// reduces epilogue write conflicts to 4-way)
#define XROWS   72            // dec layer0 input = cat(x[8], y_prev[64])
#define RS      68            // row stride for xs/hs
#define XS_F    (XROWS*RS)            // 4896
#define HS_F    (3*Hz*RS)             // 13056
#define CS_F    (3*Hz*BT)             // 12288
#define GS_F    (BT*Gz)               // 16384
#define FW_F    (Dz*Hz)               // 512
#define SMEM_FLOATS (XS_F + HS_F + CS_F + GS_F + FW_F + 8)
#define SMEM_BYTES  (SMEM_FLOATS * 4)

// ---------------- f32x2 helpers ----------------
__device__ __forceinline__ unsigned long long pack2(float x, float y) {
    unsigned long long r;
    asm("mov.b64 %0, {%1, %2};" : "=l"(r) : "r"(__float_as_uint(x)), "r"(__float_as_uint(y)));
    return r;
}
__device__ __forceinline__ void unpack2(unsigned long long v, float& x, float& y) {
    unsigned lo, hi;
    asm("mov.b64 {%0, %1}, %2;" : "=r"(lo), "=r"(hi) : "l"(v));
    x = __uint_as_float(lo); y = __uint_as_float(hi);
}
__device__ __forceinline__ void ffma2(unsigned long long& a, unsigned long long w, unsigned long long v) {
    asm("fma.rn.f32x2 %0, %1, %2, %0;" : "+l"(a) : "l"(w), "l"(v));
}

// fast, accurate-enough activations (~1e-6 rel err)
__device__ __forceinline__ float sigf(float x) {
    return __fdividef(1.f, 1.f + __expf(-x));
}
__device__ __forceinline__ float tanh_(float x) {
    x = fminf(15.f, fmaxf(-15.f, x));
    float t = __expf(-2.f * x);
    return __fdividef(1.f - t, 1.f + t);
}

// Accumulate acc[b] += W_row[k] * s[k][b] over nch chunks of 8 k-values.
// s rows have stride RS floats; all threads read the same address per load (broadcast).
// Weight quads are double-buffered (prefetch next chunk during compute).
__device__ __forceinline__ void accum8(const float* __restrict__ W,
                                       const float* __restrict__ s,
                                       int nch,
                                       unsigned long long acc[32]) {
    float4 wa = *(const float4*)(W);
    float4 wb = *(const float4*)(W + 4);
    for (int c = 0; c < nch; ++c) {
        float4 na = wa, nb = wb;
        if (c + 1 < nch) {
            na = *(const float4*)(W + (c + 1) * 8);
            nb = *(const float4*)(W + (c + 1) * 8 + 4);
        }
        unsigned long long wp[8];
        wp[0] = pack2(wa.x, wa.x); wp[1] = pack2(wa.y, wa.y);
        wp[2] = pack2(wa.z, wa.z); wp[3] = pack2(wa.w, wa.w);
        wp[4] = pack2(wb.x, wb.x); wp[5] = pack2(wb.y, wb.y);
        wp[6] = pack2(wb.z, wb.z); wp[7] = pack2(wb.w, wb.w);
        const float* base = s + c * 8 * RS;
        #pragma unroll
        for (int k = 0; k < 8; ++k) {
            const ulonglong2* row = (const ulonglong2*)(base + k * RS);
            #pragma unroll
            for (int bq = 0; bq < 16; ++bq) {
                ulonglong2 v = row[bq];
                ffma2(acc[2 * bq],     wp[k], v.x);
                ffma2(acc[2 * bq + 1], wp[k], v.y);
            }
        }
        wa = na; wb = nb;
    }
}

// Gate compute for thread j (one gate row, all 64 batch elems in regs)
__device__ __forceinline__ void layer_gates(int j,
                                            const float* __restrict__ Wih,
                                            const float* __restrict__ Whh,
                                            const float* __restrict__ bias,
                                            int nch_in,
                                            const float* __restrict__ in_s,
                                            const float* __restrict__ h_s,
                                            float* __restrict__ gs) {
    unsigned long long acc[32];
    float bj = bias[j];
    unsigned long long bp = pack2(bj, bj);
    #pragma unroll
    for (int i = 0; i < 32; ++i) acc[i] = bp;
    accum8(Wih + (size_t)j * (nch_in * 8), in_s, nch_in, acc);
    accum8(Whh + (size_t)j * Hz, h_s, Hz / 8, acc);
    #pragma unroll
    for (int i = 0; i < 32; ++i) {
        float lo, hi;
        unpack2(acc[i], lo, hi);
        gs[(2 * i) * Gz + j]     = lo;
        gs[(2 * i + 1) * Gz + j] = hi;
    }
}

// LSTM pointwise epilogue: thread handles unit u = tid&63, batch group tid>>6 (16 b each)
__device__ __forceinline__ void layer_epilogue(int tid,
                                               const float* __restrict__ gs,
                                               float* __restrict__ c_s,   // [b*64+u]
                                               float* __restrict__ h_s,   // [u*RS+b]
                                               float* __restrict__ y_s) { // optional copy
    int u = tid & 63, grp = tid >> 6;
    #pragma unroll 4
    for (int bi = 0; bi < 16; ++bi) {
        int b = grp * 16 + bi;
        float gi = gs[b * Gz + u];
        float gf = gs[b * Gz + 64 + u];
        float gg = gs[b * Gz + 128 + u];
        float go = gs[b * Gz + 192 + u];
        float c  = c_s[b * Hz + u];
        float cn = sigf(gf) * c + sigf(gi) * tanh_(gg);
        float hn = sigf(go) * tanh_(cn);
        c_s[b * Hz + u]  = cn;
        h_s[u * RS + b]  = hn;
        if (y_s) y_s[u * RS + b] = hn;
    }
}

// Final FC: pred[b][d] = h[b] . fc_W[d] + fc_b[d]
__device__ __forceinline__ void fc_store(int tid,
                                         const float* __restrict__ h_s,
                                         const float* __restrict__ fw,
                                         const float* __restrict__ fb,
                                         float* __restrict__ out,
                                         int b0, int t) {
    int b = tid & 63, dd = tid >> 6;  // dd in 0..3, handles d=dd and d=dd+4
    float a0 = fb[dd], a1 = fb[dd + 4];
    #pragma unroll
    for (int u = 0; u < Hz; ++u) {
        float h = h_s[u * RS + b];
        a0 = fmaf(fw[dd * Hz + u], h, a0);
        a1 = fmaf(fw[(dd + 4) * Hz + u], h, a1);
    }
    float* o = out + ((size_t)(b0 + b) * Tz + t) * Dz;
    o[dd]     = a0;
    o[dd + 4] = a1;
}

__global__ void __launch_bounds__(NTHR, 1)
seq2seq_kernel(const float* __restrict__ enc_x, const float* __restrict__ dec_x,
               const float* __restrict__ eWih0, const float* __restrict__ eWhh0, const float* __restrict__ eb0,
               const float* __restrict__ eWih1, const float* __restrict__ eWhh1, const float* __restrict__ eb1,
               const float* __restrict__ eWih2, const float* __restrict__ eWhh2, const float* __restrict__ eb2,
               const float* __restrict__ dWih0, const float* __restrict__ dWhh0, const float* __restrict__ db0,
               const float* __restrict__ dWih1, const float* __restrict__ dWhh1, const float* __restrict__ db1,
               const float* __restrict__ dWih2, const float* __restrict__ dWhh2, const float* __restrict__ db2,
               const float* __restrict__ fcW, const float* __restrict__ fcb,
               float* __restrict__ out) {
    extern __shared__ float sm[];
    float* xs  = sm;                    // [XROWS][RS] layer-0 input, transposed
    float* hs  = xs + XS_F;             // 3 x [64][RS] h state, transposed
    float* cs  = hs + HS_F;             // 3 x [b*64+u] c state
    float* gs  = cs + CS_F;             // [b][256] gate scratch
    float* fw  = gs + GS_F;             // fc weights
    float* fb  = fw + FW_F;             // fc bias

    const int tid = threadIdx.x;
    const int b0  = blockIdx.x * BT;

    // init state + fc cache
    for (int i = tid; i < HS_F; i += NTHR) hs[i] = 0.f;
    for (int i = tid; i < CS_F; i += NTHR) cs[i] = 0.f;
    for (int i = tid; i < FW_F; i += NTHR) fw[i] = fcW[i];
    if (tid < Dz) fb[tid] = fcb[tid];
    __syncthreads();

    float* hs0 = hs;           float* hs1 = hs + Hz * RS;  float* hs2 = hs + 2 * Hz * RS;
    float* cs0 = cs;           float* cs1 = cs + Hz * BT;  float* cs2 = cs + 2 * Hz * BT;

    #pragma unroll 1
    for (int phase = 0; phase < 2; ++phase) {
        const float* xp = phase ? dec_x : enc_x;
        const float* W0 = phase ? dWih0 : eWih0; const float* U0 = phase ? dWhh0 : eWhh0; const float* B0 = phase ? db0 : eb0;
        const float* W1 = phase ? dWih1 : eWih1; const float* U1 = phase ? dWhh1 : eWhh1; const float* B1 = phase ? db1 : eb1;
        const float* W2 = phase ? dWih2 : eWih2; const float* U2 = phase ? dWhh2 : eWhh2; const float* B2 = phase ? db2 : eb2;
        const int nch0 = phase ? 9 : 1;   // layer-0 input width / 8  (72 or 8)
        float* ybuf = phase ? (xs + Dz * RS) : (float*)0;

        if (phase == 1) {
            // y_prev = 0 for first decoder step (xs rows 8..71)
            for (int i = tid; i < Hz * RS; i += NTHR) xs[Dz * RS + i] = 0.f;
        }
        __syncthreads();

        #pragma unroll 1
        for (int t = 0; t < Tz; ++t) {
            // stage x_t transposed: xs[k][b], k in 0..7
            {
                int b = tid & 63, k = tid >> 6;
                const float* src = xp + ((size_t)(b0 + b) * Tz + t) * Dz;
                xs[k * RS + b]       = src[k];
                xs[(k + 4) * RS + b] = src[k + 4];
            }
            __syncthreads();

            // layer 0
            layer_gates(tid, W0, U0, B0, nch0, xs, hs0, gs);
            __syncthreads();
            layer_epilogue(tid, gs, cs0, hs0, (float*)0);
            __syncthreads();
            // layer 1
            layer_gates(tid, W1, U1, B1, 8, hs0, hs1, gs);
            __syncthreads();
            layer_epilogue(tid, gs, cs1, hs1, (float*)0);
            __syncthreads();
            // layer 2 (decoder: also write y into xs rows 8..71 for next step)
            layer_gates(tid, W2, U2, B2, 8, hs1, hs2, gs);
            __syncthreads();
            layer_epilogue(tid, gs, cs2, hs2, ybuf);
            __syncthreads();

            if (phase == 1) fc_store(tid, hs2, fw, fb, out, b0, t);
        }
    }
}

extern "C" void kernel_launch(void* const* d_in, const int* in_sizes, int n_in,
                              void* d_out, int out_size) {
    (void)in_sizes; (void)n_in; (void)out_size;
    const float* enc_x = (const float*)d_in[0];
    const float* dec_x = (const float*)d_in[1];
    const float* eWih0 = (const float*)d_in[2];
    const float* eWhh0 = (const float*)d_in[3];
    const float* eb0   = (const float*)d_in[4];
    const float* eWih1 = (const float*)d_in[5];
    const float* eWhh1 = (const float*)d_in[6];
    const float* eb1   = (const float*)d_in[7];
    const float* eWih2 = (const float*)d_in[8];
    const float* eWhh2 = (const float*)d_in[9];
    const float* eb2   = (const float*)d_in[10];
    const float* dWih0 = (const float*)d_in[11];
    const float* dWhh0 = (const float*)d_in[12];
    const float* db0   = (const float*)d_in[13];
    const float* dWih1 = (const float*)d_in[14];
    const float* dWhh1 = (const float*)d_in[15];
    const float* db1   = (const float*)d_in[16];
    const float* dWih2 = (const float*)d_in[17];
    const float* dWhh2 = (const float*)d_in[18];
    const float* db2   = (const float*)d_in[19];
    const float* fcW   = (const float*)d_in[20];
    const float* fcb   = (const float*)d_in[21];
    float* out = (float*)d_out;

    cudaFuncSetAttribute(seq2seq_kernel,
                         cudaFuncAttributeMaxDynamicSharedMemorySize, SMEM_BYTES);

    seq2seq_kernel<<<NCTA, NTHR, SMEM_BYTES>>>(
        enc_x, dec_x,
        eWih0, eWhh0, eb0, eWih1, eWhh1, eb1, eWih2, eWhh2, eb2,
        dWih0, dWhh0, db0, dWih1, dWhh1, db1, dWih2, dWhh2, db2,
        fcW, fcb, out);
}

// round 7
// speedup vs baseline: 1.2759x; 1.2759x over previous
#include <cuda_runtime.h>
#include <cstdint>

// Problem constants
#define Bz   8192
#define Tz   512
#define Dz   8
#define Hz   64
#define Gz   256      // 4*H
#define BT   64       // batch tile per CTA
#define NCTA 128      // Bz / BT
#define NTHR 256

// SMEM layout (floats)
#define XROWS   72            // dec layer0 input = cat(x[8], y_prev[64])
#define RS      68            // row stride for xs/hs (16B aligned rows)
#define GSTR    66            // gs row stride (8B aligned, 2-way conflicts only)
#define XS_F    (XROWS*RS)            // 4896
#define HS_F    (3*Hz*RS)             // 13056
#define CS_F    (3*Hz*BT)             // 12288
#define GS_F    (Gz*GSTR)             // 16896
#define FW_F    (Dz*Hz)               // 512
#define SMEM_FLOATS (XS_F + HS_F + CS_F + GS_F + FW_F + 16)
#define SMEM_BYTES  (SMEM_FLOATS * 4)

typedef unsigned long long u64;

// Pre-transposed, pre-duplicated weights: element (k2*256 + j) holds
// { {w[j][2k2], w[j][2k2]}, {w[j][2k2+1], w[j][2k2+1]} }
__device__ ulonglong2 g_wt[92160];   // 1.44 MB

// offsets (ulonglong2 units) per matrix, fan2*256 each
#define O_EI0 0        // fan2=4
#define O_EH0 1024     // 32
#define O_EI1 9216     // 32
#define O_EH1 17408    // 32
#define O_EI2 25600    // 32
#define O_EH2 33792    // 32
#define O_DI0 41984    // 36
#define O_DH0 51200    // 32
#define O_DI1 59392    // 32
#define O_DH1 67584    // 32
#define O_DI2 75776    // 32
#define O_DH2 83968    // 32

// ---------------- helpers ----------------
__device__ __forceinline__ u64 pack2(float x, float y) {
    u64 r;
    asm("mov.b64 %0, {%1, %2};" : "=l"(r) : "r"(__float_as_uint(x)), "r"(__float_as_uint(y)));
    return r;
}
__device__ __forceinline__ void ffma2(u64& a, u64 w, u64 v) {
    asm("fma.rn.f32x2 %0, %1, %2, %0;" : "+l"(a) : "l"(w), "l"(v));
}
__device__ __forceinline__ float tanhx(float x) {
    float r;
    asm("tanh.approx.f32 %0, %1;" : "=f"(r) : "f"(x));
    return r;
}
__device__ __forceinline__ float sigx(float x) {
    return fmaf(tanhx(0.5f * x), 0.5f, 0.5f);
}

// ---------------- weight prep ----------------
__global__ void prep_kernel(const float* __restrict__ W, int fan, int off) {
    int id = blockIdx.x * 256 + threadIdx.x;   // id = k2*256 + j ; grid.x == fan/2
    int k2 = id >> 8, j = id & 255;
    float w0 = W[j * fan + 2 * k2];
    float w1 = W[j * fan + 2 * k2 + 1];
    ulonglong2 o;
    o.x = pack2(w0, w0);
    o.y = pack2(w1, w1);
    g_wt[off + id] = o;
}

// ---------------- gate accumulation ----------------
// acc[b] += W[row][k] * s[k][b]; thread handles rows jj and jj+128, batches [ho, ho+32)
template<int FAN2>
__device__ __forceinline__ void accum_mat(const ulonglong2* __restrict__ Wt, int jj,
                                          const float* __restrict__ s, int ho,
                                          u64* __restrict__ accA, u64* __restrict__ accB) {
    const ulonglong2* pA = Wt + jj;
    const ulonglong2* pB = Wt + jj + 128;
    ulonglong2 bufA[2], bufB[2];
    bufA[0] = pA[0]; bufB[0] = pB[0];
    if (FAN2 > 1) { bufA[1] = pA[256]; bufB[1] = pB[256]; }
    #pragma unroll 2
    for (int k2 = 0; k2 < FAN2; ++k2) {
        ulonglong2 wA = bufA[k2 & 1], wB = bufB[k2 & 1];
        if (k2 + 2 < FAN2) {
            bufA[k2 & 1] = pA[(k2 + 2) * 256];
            bufB[k2 & 1] = pB[(k2 + 2) * 256];
        }
        const ulonglong2* s0 = (const ulonglong2*)(s + (2 * k2) * RS + ho);
        const ulonglong2* s1 = (const ulonglong2*)(s + (2 * k2 + 1) * RS + ho);
        #pragma unroll
        for (int q = 0; q < 8; ++q) {
            ulonglong2 v0 = s0[q];
            ffma2(accA[2 * q],     wA.x, v0.x);
            ffma2(accA[2 * q + 1], wA.x, v0.y);
            ffma2(accB[2 * q],     wB.x, v0.x);
            ffma2(accB[2 * q + 1], wB.x, v0.y);
            ulonglong2 v1 = s1[q];
            ffma2(accA[2 * q],     wA.y, v1.x);
            ffma2(accA[2 * q + 1], wA.y, v1.y);
            ffma2(accB[2 * q],     wB.y, v1.x);
            ffma2(accB[2 * q + 1], wB.y, v1.y);
        }
    }
}

template<int FANIH2>
__device__ __forceinline__ void layer_gates(int tid,
                                            const ulonglong2* __restrict__ WtIh,
                                            const ulonglong2* __restrict__ WtHh,
                                            const float* __restrict__ bias,
                                            const float* __restrict__ in_s,
                                            const float* __restrict__ h_s,
                                            float* __restrict__ gs) {
    int jj = tid & 127, half = tid >> 7, ho = half * 32;
    u64 accA[16], accB[16];
    float bA = bias[jj], bB = bias[jj + 128];
    u64 bpA = pack2(bA, bA), bpB = pack2(bB, bB);
    #pragma unroll
    for (int i = 0; i < 16; ++i) { accA[i] = bpA; accB[i] = bpB; }
    accum_mat<FANIH2>(WtIh, jj, in_s, ho, accA, accB);
    accum_mat<32>(WtHh, jj, h_s, ho, accA, accB);
    float* gA = gs + jj * GSTR + ho;
    float* gB = gs + (jj + 128) * GSTR + ho;
    #pragma unroll
    for (int q = 0; q < 16; ++q) {
        *(u64*)(gA + 2 * q) = accA[q];   // {b_even, b_odd} little-endian == gs[b], gs[b+1]
        *(u64*)(gB + 2 * q) = accB[q];
    }
}

// LSTM pointwise epilogue: thread handles unit u = tid&63, batch group tid>>6 (16 b each)
__device__ __forceinline__ void layer_epilogue(int tid,
                                               const float* __restrict__ gs,
                                               float* __restrict__ c_s,   // [b*64+u]
                                               float* __restrict__ h_s,   // [u*RS+b]
                                               float* __restrict__ y_s) { // optional copy
    int u = tid & 63, grp = tid >> 6;
    #pragma unroll 4
    for (int bi = 0; bi < 16; ++bi) {
        int b = grp * 16 + bi;
        float gi = gs[u * GSTR + b];
        float gf = gs[(u + 64) * GSTR + b];
        float gg = gs[(u + 128) * GSTR + b];
        float go = gs[(u + 192) * GSTR + b];
        float c  = c_s[b * Hz + u];
        float cn = sigx(gf) * c + sigx(gi) * tanhx(gg);
        float hn = sigx(go) * tanhx(cn);
        c_s[b * Hz + u] = cn;
        h_s[u * RS + b] = hn;
        if (y_s) y_s[u * RS + b] = hn;
    }
}

// Final FC: pred[b][d] = h[b] . fc_W[d] + fc_b[d]
__device__ __forceinline__ void fc_store(int tid,
                                         const float* __restrict__ h_s,
                                         const float* __restrict__ fw,
                                         const float* __restrict__ fb,
                                         float* __restrict__ out,
                                         int b0, int t) {
    int b = tid & 63, dd = tid >> 6;  // dd in 0..3, handles d=dd and d=dd+4
    float a0 = fb[dd], a1 = fb[dd + 4];
    #pragma unroll
    for (int u = 0; u < Hz; ++u) {
        float h = h_s[u * RS + b];
        a0 = fmaf(fw[dd * Hz + u], h, a0);
        a1 = fmaf(fw[(dd + 4) * Hz + u], h, a1);
    }
    float* o = out + ((size_t)(b0 + b) * Tz + t) * Dz;
    o[dd]     = a0;
    o[dd + 4] = a1;
}

__global__ void __launch_bounds__(NTHR, 1)
seq2seq_kernel(const float* __restrict__ enc_x, const float* __restrict__ dec_x,
               const float* __restrict__ eb0, const float* __restrict__ eb1, const float* __restrict__ eb2,
               const float* __restrict__ db0, const float* __restrict__ db1, const float* __restrict__ db2,
               const float* __restrict__ fcW, const float* __restrict__ fcb,
               float* __restrict__ out) {
    extern __shared__ float sm[];
    float* xs = sm;                 // [XROWS][RS] layer-0 input, transposed
    float* hs = xs + XS_F;          // 3 x [64][RS] h state, transposed
    float* cs = hs + HS_F;          // 3 x [b*64+u]
    float* gs = cs + CS_F;          // [256][GSTR]
    float* fw = gs + GS_F;
    float* fb = fw + FW_F;

    const int tid = threadIdx.x;
    const int b0  = blockIdx.x * BT;

    for (int i = tid; i < HS_F; i += NTHR) hs[i] = 0.f;
    for (int i = tid; i < CS_F; i += NTHR) cs[i] = 0.f;
    for (int i = tid; i < FW_F; i += NTHR) fw[i] = fcW[i];
    if (tid < Dz) fb[tid] = fcb[tid];
    __syncthreads();

    float* hs0 = hs;          float* hs1 = hs + Hz * RS;  float* hs2 = hs + 2 * Hz * RS;
    float* cs0 = cs;          float* cs1 = cs + Hz * BT;  float* cs2 = cs + 2 * Hz * BT;

    // ---------------- encoder ----------------
    {
        const ulonglong2* WI0 = g_wt + O_EI0; const ulonglong2* WH0 = g_wt + O_EH0;
        const ulonglong2* WI1 = g_wt + O_EI1; const ulonglong2* WH1 = g_wt + O_EH1;
        const ulonglong2* WI2 = g_wt + O_EI2; const ulonglong2* WH2 = g_wt + O_EH2;

        #pragma unroll 1
        for (int t = 0; t < Tz; ++t) {
            {
                int b = tid & 63, k = tid >> 6;
                const float* src = enc_x + ((size_t)(b0 + b) * Tz + t) * Dz;
                xs[k * RS + b]       = src[k];
                xs[(k + 4) * RS + b] = src[k + 4];
            }
            __syncthreads();
            layer_gates<4>(tid, WI0, WH0, eb0, xs, hs0, gs);
            __syncthreads();
            layer_epilogue(tid, gs, cs0, hs0, (float*)0);
            __syncthreads();
            layer_gates<32>(tid, WI1, WH1, eb1, hs0, hs1, gs);
            __syncthreads();
            layer_epilogue(tid, gs, cs1, hs1, (float*)0);
            __syncthreads();
            layer_gates<32>(tid, WI2, WH2, eb2, hs1, hs2, gs);
            __syncthreads();
            layer_epilogue(tid, gs, cs2, hs2, (float*)0);
            __syncthreads();
        }
    }

    // ---------------- decoder ----------------
    {
        const ulonglong2* WI0 = g_wt + O_DI0; const ulonglong2* WH0 = g_wt + O_DH0;
        const ulonglong2* WI1 = g_wt + O_DI1; const ulonglong2* WH1 = g_wt + O_DH1;
        const ulonglong2* WI2 = g_wt + O_DI2; const ulonglong2* WH2 = g_wt + O_DH2;
        float* ybuf = xs + Dz * RS;

        for (int i = tid; i < Hz * RS; i += NTHR) ybuf[i] = 0.f;  // y_prev = 0
        __syncthreads();

        #pragma unroll 1
        for (int t = 0; t < Tz; ++t) {
            {
                int b = tid & 63, k = tid >> 6;
                const float* src = dec_x + ((size_t)(b0 + b) * Tz + t) * Dz;
                xs[k * RS + b]       = src[k];
                xs[(k + 4) * RS + b] = src[k + 4];
            }
            __syncthreads();
            layer_gates<36>(tid, WI0, WH0, db0, xs, hs0, gs);
            __syncthreads();
            layer_epilogue(tid, gs, cs0, hs0, (float*)0);
            __syncthreads();
            layer_gates<32>(tid, WI1, WH1, db1, hs0, hs1, gs);
            __syncthreads();
            layer_epilogue(tid, gs, cs1, hs1, (float*)0);
            __syncthreads();
            layer_gates<32>(tid, WI2, WH2, db2, hs1, hs2, gs);
            __syncthreads();
            layer_epilogue(tid, gs, cs2, hs2, ybuf);
            __syncthreads();

            fc_store(tid, hs2, fw, fb, out, b0, t);
        }
    }
}

extern "C" void kernel_launch(void* const* d_in, const int* in_sizes, int n_in,
                              void* d_out, int out_size) {
    (void)in_sizes; (void)n_in; (void)out_size;
    const float* enc_x = (const float*)d_in[0];
    const float* dec_x = (const float*)d_in[1];
    const float* eWih0 = (const float*)d_in[2];
    const float* eWhh0 = (const float*)d_in[3];
    const float* eb0   = (const float*)d_in[4];
    const float* eWih1 = (const float*)d_in[5];
    const float* eWhh1 = (const float*)d_in[6];
    const float* eb1   = (const float*)d_in[7];
    const float* eWih2 = (const float*)d_in[8];
    const float* eWhh2 = (const float*)d_in[9];
    const float* eb2   = (const float*)d_in[10];
    const float* dWih0 = (const float*)d_in[11];
    const float* dWhh0 = (const float*)d_in[12];
    const float* db0   = (const float*)d_in[13];
    const float* dWih1 = (const float*)d_in[14];
    const float* dWhh1 = (const float*)d_in[15];
    const float* db1   = (const float*)d_in[16];
    const float* dWih2 = (const float*)d_in[17];
    const float* dWhh2 = (const float*)d_in[18];
    const float* db2   = (const float*)d_in[19];
    const float* fcW   = (const float*)d_in[20];
    const float* fcb   = (const float*)d_in[21];
    float* out = (float*)d_out;

    // weight transpose+duplicate prep (12 tiny launches, graph-capturable)
    prep_kernel<<< 4, 256>>>(eWih0,  8, O_EI0);
    prep_kernel<<<32, 256>>>(eWhh0, 64, O_EH0);
    prep_kernel<<<32, 256>>>(eWih1, 64, O_EI1);
    prep_kernel<<<32, 256>>>(eWhh1, 64, O_EH1);
    prep_kernel<<<32, 256>>>(eWih2, 64, O_EI2);
    prep_kernel<<<32, 256>>>(eWhh2, 64, O_EH2);
    prep_kernel<<<36, 256>>>(dWih0, 72, O_DI0);
    prep_kernel<<<32, 256>>>(dWhh0, 64, O_DH0);
    prep_kernel<<<32, 256>>>(dWih1, 64, O_DI1);
    prep_kernel<<<32, 256>>>(dWhh1, 64, O_DH1);
    prep_kernel<<<32, 256>>>(dWih2, 64, O_DI2);
    prep_kernel<<<32, 256>>>(dWhh2, 64, O_DH2);

    cudaFuncSetAttribute(seq2seq_kernel,
                         cudaFuncAttributeMaxDynamicSharedMemorySize, SMEM_BYTES);
    seq2seq_kernel<<<NCTA, NTHR, SMEM_BYTES>>>(
        enc_x, dec_x, eb0, eb1, eb2, db0, db1, db2, fcW, fcb, out);
}